// round 13
// baseline (speedup 1.0000x reference)
#include <cuda_runtime.h>
#include <cuda_fp16.h>
#include <math_constants.h>
#include <cstdint>

// Problem constants
constexpr int BB  = 2;
constexpr int NN  = 2048;
constexpr int DD  = 1024;
constexpr int HH  = 16;
constexpr int RR  = 32;
constexpr int DK  = 64;
constexpr int HR  = HH * RR;      // 512
constexpr int BN  = BB * NN;      // 4096
constexpr int QLD = 2 * DD;       // fused qkv row stride (2048)

constexpr float LOG2E = 1.4426950408889634f;

// Scratch (device globals; no allocation allowed)
__device__ __half g_xh[BN * DD];            // x fp16
__device__ __half g_wB[2 * DD * DD];        // rows 0..511 WqT | 512..1023 WkT | 1024..2047 Wv
__device__ __half g_wph[DD * DD];           // Wproj fp16 [n][k]
__device__ __half g_qkv[BN * QLD];          // cols: 0..511 q | 512..1023 k | 1024..2047 v
__device__ __half g_vt[BB * HH * DK * NN];  // [b][h][d][n]
__device__ __half g_zh[BN * DD];            // [bn][h*64+d]
__device__ __half g_maskh[NN * NN];         // mask * log2(e), fp16

// ---------------------------------------------------------------------------
// helpers
// ---------------------------------------------------------------------------
__device__ __forceinline__ uint32_t smem_u32(const void* p) {
    uint32_t a;
    asm("{ .reg .u64 t; cvta.to.shared.u64 t, %1; cvt.u32.u64 %0, t; }"
        : "=r"(a) : "l"(p));
    return a;
}
__device__ __forceinline__ void cp16(uint32_t s, const void* g) {
    asm volatile("cp.async.cg.shared.global [%0], [%1], 16;"
                 :: "r"(s), "l"(g) : "memory");
}
#define CP_COMMIT() asm volatile("cp.async.commit_group;" ::: "memory")
#define CP_WAIT0()  asm volatile("cp.async.wait_group 0;" ::: "memory")
#define CP_WAIT1()  asm volatile("cp.async.wait_group 1;" ::: "memory")

// single-MUFU exp2 (guaranteed, independent of compiler flags)
__device__ __forceinline__ float ex2f(float x) {
    float y; asm("ex2.approx.ftz.f32 %0, %1;" : "=f"(y) : "f"(x)); return y;
}

// D += A(16x16,row) * B(16x8,col)   fp16 inputs, f32 accum
__device__ __forceinline__ void mma_f16(float d[4], const uint32_t a[4],
                                        const uint32_t b[2]) {
    asm volatile(
        "mma.sync.aligned.m16n8k16.row.col.f32.f16.f16.f32 "
        "{%0,%1,%2,%3}, {%4,%5,%6,%7}, {%8,%9}, {%0,%1,%2,%3};"
        : "+f"(d[0]), "+f"(d[1]), "+f"(d[2]), "+f"(d[3])
        : "r"(a[0]), "r"(a[1]), "r"(a[2]), "r"(a[3]), "r"(b[0]), "r"(b[1]));
}
__device__ __forceinline__ uint32_t pack_h2(float a, float b) {
    __half2 h = __floats2half2_rn(a, b);
    return *(uint32_t*)&h;
}

// ---------------------------------------------------------------------------
// f32 -> f16 conversion (with optional scale)
// ---------------------------------------------------------------------------
__global__ void tohalf_kernel(const float* __restrict__ src,
                              __half* __restrict__ dst, int n4, float scale)
{
    int i = blockIdx.x * blockDim.x + threadIdx.x;
    if (i < n4) {
        float4 v = ((const float4*)src)[i];
        uint2 o;
        o.x = pack_h2(v.x * scale, v.y * scale);
        o.y = pack_h2(v.z * scale, v.w * scale);
        ((uint2*)dst)[i] = o;
    }
}

// ---------------------------------------------------------------------------
// Effective low-rank weights -> fp16 into g_wB:
// wB[sel*512 + h*32 + r, d] = sum_kk Wsel[(h*64+kk), d] * U[kk, r]
// grid (DD/256, HH, 4): z = sel*2 + rhalf
// ---------------------------------------------------------------------------
__global__ void weff_h_kernel(const float* __restrict__ Wq,
                              const float* __restrict__ Wk,
                              const float* __restrict__ U,
                              __half* __restrict__ wB)
{
    __shared__ float Us[DK][RR];
    const int d = blockIdx.x * 256 + threadIdx.x;
    const int h = blockIdx.y;
    const int sel = blockIdx.z >> 1, rh = blockIdx.z & 1;
    const float* W = sel ? Wk : Wq;
    for (int i = threadIdx.x; i < DK * RR; i += 256)
        Us[i >> 5][i & 31] = U[i];
    __syncthreads();

    float w[DK];
#pragma unroll
    for (int kk = 0; kk < DK; kk++)
        w[kk] = W[(size_t)(h * DK + kk) * DD + d];
#pragma unroll 1
    for (int ri = 0; ri < 16; ri++) {
        int r = rh * 16 + ri;
        float s = 0.f;
#pragma unroll
        for (int kk = 0; kk < DK; kk++) s = fmaf(w[kk], Us[kk][r], s);
        wB[(size_t)(sel * HR + h * RR + r) * DD + d] = __float2half(s);
    }
}

// ---------------------------------------------------------------------------
// V transpose: qkv v-cols [bn][1024 + h*64+d] -> vt[b][h][d][n]
// grid (NN/64, HH, BB), block 256
// ---------------------------------------------------------------------------
__global__ void vtrans_kernel(const __half* __restrict__ qkv,
                              __half* __restrict__ vt)
{
    __shared__ __half ts[64][72];
    const int b = blockIdx.z, h = blockIdx.y, n0 = blockIdx.x * 64;
    const int t = threadIdx.x;
#pragma unroll
    for (int s = 0; s < 2; s++) {
        int f = t + 256 * s, row = f >> 3, cc = (f & 7) * 8;
        *(uint4*)&ts[row][cc] = *(const uint4*)
            (qkv + (size_t)(b * NN + n0 + row) * QLD + DD + h * DK + cc);
    }
    __syncthreads();
#pragma unroll
    for (int s = 0; s < 2; s++) {
        int f = t + 256 * s, dr = f >> 3, cc = (f & 7) * 8;
        __half tmp[8];
#pragma unroll
        for (int j = 0; j < 8; j++) tmp[j] = ts[cc + j][dr];
        *(uint4*)(vt + ((size_t)((b * HH + h) * DK + dr)) * NN + n0 + cc) =
            *(uint4*)tmp;
    }
}

// ---------------------------------------------------------------------------
// fp16 HMMA GEMM with cp.async double buffering (scalar LDS fragments).
// C[M,N] = A[M,K] @ B[N,K]^T   (A,B half, K-major)
// grid (N/128, M/128), block 256 (8 warps), warp tile 32x64, K-chunk 64.
// ---------------------------------------------------------------------------
constexpr int HP      = 72;                 // smem row pitch (halfs)
constexpr int HTILE_B = 128 * HP * 2;       // 18432 bytes
constexpr int HGEMM_SMEM = 2 * 2 * HTILE_B; // 73728

__global__ __launch_bounds__(256, 2) void hgemm(
    const __half* __restrict__ A, const __half* __restrict__ B,
    float* __restrict__ Cf, __half* __restrict__ Ch, int K, int ldc,
    int out_half)
{
    extern __shared__ char sm[];
    const uint32_t smb = smem_u32(sm);
    const int t = threadIdx.x, wid = t >> 5, lane = t & 31;
    const int gr = lane >> 2, tq = lane & 3;
    const int wm = wid & 3, wn = wid >> 2;
    const int brow = blockIdx.y * 128, bcol = blockIdx.x * 128;

    const __half* Ab = A + (size_t)brow * K;
    const __half* Bb = B + (size_t)bcol * K;
    const int row_l = t >> 3, cc_l = (t & 7) * 8;

    float acc[2][8][4] = {};
    const int nc = K / 64;

    auto issue = [&](int c) {
        const int buf = c & 1, k0 = c * 64;
        uint32_t as = smb + (uint32_t)buf * (2 * HTILE_B);
        uint32_t bs = as + HTILE_B;
#pragma unroll
        for (int s = 0; s < 4; s++) {
            int row = row_l + 32 * s;
            cp16(as + (row * HP + cc_l) * 2, Ab + (size_t)row * K + k0 + cc_l);
            cp16(bs + (row * HP + cc_l) * 2, Bb + (size_t)row * K + k0 + cc_l);
        }
        CP_COMMIT();
    };

    issue(0);
    for (int c = 0; c < nc; c++) {
        __syncthreads();
        if (c + 1 < nc) { issue(c + 1); CP_WAIT1(); }
        else            { CP_WAIT0(); }
        __syncthreads();

        const __half* As = (const __half*)(sm + (c & 1) * 2 * HTILE_B);
        const __half* Bs = (const __half*)(sm + (c & 1) * 2 * HTILE_B + HTILE_B);
#pragma unroll
        for (int ks = 0; ks < 4; ks++) {
            const int kb = ks * 16;
            uint32_t af[2][4], bf[8][2];
#pragma unroll
            for (int mt = 0; mt < 2; mt++) {
                int rb0 = wm * 32 + mt * 16 + gr;
                af[mt][0] = *(const uint32_t*)&As[rb0 * HP + kb + 2 * tq];
                af[mt][1] = *(const uint32_t*)&As[(rb0 + 8) * HP + kb + 2 * tq];
                af[mt][2] = *(const uint32_t*)&As[rb0 * HP + kb + 2 * tq + 8];
                af[mt][3] = *(const uint32_t*)&As[(rb0 + 8) * HP + kb + 2 * tq + 8];
            }
#pragma unroll
            for (int nt = 0; nt < 8; nt++) {
                int cb = wn * 64 + nt * 8 + gr;
                bf[nt][0] = *(const uint32_t*)&Bs[cb * HP + kb + 2 * tq];
                bf[nt][1] = *(const uint32_t*)&Bs[cb * HP + kb + 2 * tq + 8];
            }
#pragma unroll
            for (int mt = 0; mt < 2; mt++)
#pragma unroll
                for (int nt = 0; nt < 8; nt++)
                    mma_f16(acc[mt][nt], af[mt], bf[nt]);
        }
    }

#pragma unroll
    for (int mt = 0; mt < 2; mt++) {
        int r0 = brow + wm * 32 + mt * 16 + gr;
#pragma unroll
        for (int nt = 0; nt < 8; nt++) {
            int col = bcol + wn * 64 + nt * 8 + 2 * tq;
            if (out_half) {
                *(uint32_t*)(Ch + (size_t)r0 * ldc + col) =
                    pack_h2(acc[mt][nt][0], acc[mt][nt][1]);
                *(uint32_t*)(Ch + (size_t)(r0 + 8) * ldc + col) =
                    pack_h2(acc[mt][nt][2], acc[mt][nt][3]);
            } else {
                *(float2*)(Cf + (size_t)r0 * ldc + col) =
                    make_float2(acc[mt][nt][0], acc[mt][nt][1]);
                *(float2*)(Cf + (size_t)(r0 + 8) * ldc + col) =
                    make_float2(acc[mt][nt][2], acc[mt][nt][3]);
            }
        }
    }
}

// ---------------------------------------------------------------------------
// Flash attention, fp16 HMMA, register-resident P, base-2 softmax (MUFU EX2),
// ones-column row sums, diagonal-aware ALiBi, conditional O rescale.
// grid (N/128, H, B), block 256 (8 warps), warp = 16 query rows.
// KV chunk = 64 keys, cp.async double buffered.
// SMEM: 2 stages x (K[64 keys][40h] + Vt[72 d-rows][72h])
// ---------------------------------------------------------------------------
constexpr int KPH = 40, VPH = 72;
constexpr int KTB = 64 * KPH * 2;        // 5120
constexpr int VTB = 72 * VPH * 2;        // 10368 (rows 64..71 = ones/zeros)
constexpr int STG = KTB + VTB;           // 15488
constexpr int ATT_SMEM = 2 * STG;        // 30976

__global__ __launch_bounds__(256, 2) void attn_h_kernel(
    const __half* __restrict__ qkv, const __half* __restrict__ vt,
    const __half* __restrict__ mask, const int* __restrict__ rbt,
    __half* __restrict__ z)
{
    extern __shared__ char sma[];
    const uint32_t smb = smem_u32(sma);

    const int t = threadIdx.x, wid = t >> 5, lane = t & 31;
    const int gr = lane >> 2, tq = lane & 3;
    const int b = blockIdx.z, h = blockIdx.y;
    const int q0 = blockIdx.x * 128;

    // base-2 domain: logits scaled by log2(e)
    const float qs     = 0.125f * LOG2E;
    const float slope2 = exp2f(-0.5f * (float)(h + 1)) * LOG2E;
    const int   Ttok   = rbt[0];

    // init ones rows (64..71) of both V stage buffers; row 64 = 1, rest 0
#pragma unroll
    for (int bi = 0; bi < 2; bi++) {
        __half* vsp = (__half*)(sma + bi * STG + KTB);
        for (int i = t; i < 8 * VPH; i += 256) {
            int row = 64 + i / VPH;
            vsp[row * VPH + (i % VPH)] =
                (row == 64) ? __float2half(1.f) : __float2half(0.f);
        }
    }

    // Q fragments (raw fp16): warp owns rows q0 + wid*16 .. +15
    const int qrow = q0 + wid * 16 + gr;
    uint32_t qa[2][4];
    {
        const __half* q0p = qkv + (size_t)(b * NN + qrow) * QLD + h * RR;
        const __half* q1p = q0p + (size_t)8 * QLD;
#pragma unroll
        for (int ks = 0; ks < 2; ks++) {
            qa[ks][0] = *(const uint32_t*)&q0p[ks * 16 + 2 * tq];
            qa[ks][1] = *(const uint32_t*)&q1p[ks * 16 + 2 * tq];
            qa[ks][2] = *(const uint32_t*)&q0p[ks * 16 + 2 * tq + 8];
            qa[ks][3] = *(const uint32_t*)&q1p[ks * 16 + 2 * tq + 8];
        }
    }

    auto issue = [&](int c) {
        const int buf = c & 1, kc = c * 64;
        uint32_t ksm = smb + (uint32_t)buf * STG;
        uint32_t vsm = ksm + KTB;
        const __half* kb = qkv + (size_t)(b * NN + kc) * QLD + HR + h * RR;
        const __half* vb = vt + ((size_t)((b * HH + h) * DK)) * NN + kc;
        {   // K: 64 rows x 32 halfs = 256 cp16, one per thread
            int row = t >> 2, cc = (t & 3) * 8;
            cp16(ksm + (row * KPH + cc) * 2, kb + (size_t)row * QLD + cc);
        }
#pragma unroll
        for (int s = 0; s < 2; s++) {   // V: 64 rows x 64 halfs = 512 cp16
            int f = t + 256 * s, row = f >> 3, cc = (f & 7) * 8;
            cp16(vsm + (row * VPH + cc) * 2, vb + (size_t)row * NN + cc);
        }
        CP_COMMIT();
    };

    float o[9][4] = {};                    // tile 8 = row-sum (ones column)
    float mrun[2] = {-1e30f, -1e30f};

    const int nch = NN / 64;
    issue(0);
    for (int c = 0; c < nch; c++) {
        const int kc = c * 64;
        __syncthreads();
        if (c + 1 < nch) { issue(c + 1); CP_WAIT1(); }
        else             { CP_WAIT0(); }
        __syncthreads();

        const __half* Ks = (const __half*)(sma + (c & 1) * STG);
        const __half* Vs = (const __half*)(sma + (c & 1) * STG + KTB);

        // ---- S = Q K^T ----
        float s[8][4] = {};
#pragma unroll
        for (int ks = 0; ks < 2; ks++) {
            uint32_t bf[8][2];
#pragma unroll
            for (int nt = 0; nt < 8; nt++) {
                bf[nt][0] = *(const uint32_t*)&Ks[(nt * 8 + gr) * KPH + ks * 16 + 2 * tq];
                bf[nt][1] = *(const uint32_t*)&Ks[(nt * 8 + gr) * KPH + ks * 16 + 2 * tq + 8];
            }
#pragma unroll
            for (int nt = 0; nt < 8; nt++)
                mma_f16(s[nt], qa[ks], bf[nt]);
        }

        // ---- scale + bias (diagonal-aware) + online softmax + P pack ----
        uint32_t pa[4][4];
        {
            const int base = q0 + wid * 16;        // warp-uniform min row
            const int i0 = qrow, i1 = i0 + 8;
            const float adj0 = (float)(i0 + Ttok - NN);
            const float adj1 = (float)(i1 + Ttok - NN);
            const __half* mr0 = mask + (size_t)i0 * NN;
            const __half* mr1 = mask + (size_t)i1 * NN;

            if (kc + 63 <= base + Ttok - NN) {
                // all keys at/below diagonal for every row: dist = 0
#pragma unroll
                for (int nt = 0; nt < 8; nt++) {
                    int j0 = kc + nt * 8 + 2 * tq;
                    float2 mk0 = __half22float2(*(const __half2*)(mr0 + j0));
                    float2 mk1 = __half22float2(*(const __half2*)(mr1 + j0));
                    s[nt][0] = fmaf(s[nt][0], qs, mk0.x);
                    s[nt][1] = fmaf(s[nt][1], qs, mk0.y);
                    s[nt][2] = fmaf(s[nt][2], qs, mk1.x);
                    s[nt][3] = fmaf(s[nt][3], qs, mk1.y);
                }
            } else if (kc >= base + 15 + Ttok - NN) {
                // all keys above diagonal: dist = j - adj (no clamp)
                const float c0 = slope2 * adj0, c1 = slope2 * adj1;
#pragma unroll
                for (int nt = 0; nt < 8; nt++) {
                    int j0 = kc + nt * 8 + 2 * tq;
                    float2 mk0 = __half22float2(*(const __half2*)(mr0 + j0));
                    float2 mk1 = __half22float2(*(const __half2*)(mr1 + j0));
                    float j0f = (float)j0, j1f = j0f + 1.f;
                    s[nt][0] = fmaf(s[nt][0], qs, fmaf(j0f, -slope2, mk0.x + c0));
                    s[nt][1] = fmaf(s[nt][1], qs, fmaf(j1f, -slope2, mk0.y + c0));
                    s[nt][2] = fmaf(s[nt][2], qs, fmaf(j0f, -slope2, mk1.x + c1));
                    s[nt][3] = fmaf(s[nt][3], qs, fmaf(j1f, -slope2, mk1.y + c1));
                }
            } else {
                // mixed chunk (diagonal crossing)
#pragma unroll
                for (int nt = 0; nt < 8; nt++) {
                    int j0 = kc + nt * 8 + 2 * tq;
                    float2 mk0 = __half22float2(*(const __half2*)(mr0 + j0));
                    float2 mk1 = __half22float2(*(const __half2*)(mr1 + j0));
                    float j0f = (float)j0, j1f = j0f + 1.f;
                    s[nt][0] = fmaf(s[nt][0], qs,
                                    mk0.x - slope2 * fmaxf(j0f - adj0, 0.f));
                    s[nt][1] = fmaf(s[nt][1], qs,
                                    mk0.y - slope2 * fmaxf(j1f - adj0, 0.f));
                    s[nt][2] = fmaf(s[nt][2], qs,
                                    mk1.x - slope2 * fmaxf(j0f - adj1, 0.f));
                    s[nt][3] = fmaf(s[nt][3], qs,
                                    mk1.y - slope2 * fmaxf(j1f - adj1, 0.f));
                }
            }

            float lm0 = -1e30f, lm1 = -1e30f;
#pragma unroll
            for (int nt = 0; nt < 8; nt++) {
                lm0 = fmaxf(lm0, fmaxf(s[nt][0], s[nt][1]));
                lm1 = fmaxf(lm1, fmaxf(s[nt][2], s[nt][3]));
            }
            lm0 = fmaxf(lm0, __shfl_xor_sync(0xffffffffu, lm0, 1));
            lm0 = fmaxf(lm0, __shfl_xor_sync(0xffffffffu, lm0, 2));
            lm1 = fmaxf(lm1, __shfl_xor_sync(0xffffffffu, lm1, 1));
            lm1 = fmaxf(lm1, __shfl_xor_sync(0xffffffffu, lm1, 2));

            float mn0 = fmaxf(mrun[0], lm0);
            float mn1 = fmaxf(mrun[1], lm1);
            float sc0 = ex2f(mrun[0] - mn0);
            float sc1 = ex2f(mrun[1] - mn1);
            mrun[0] = mn0; mrun[1] = mn1;

#pragma unroll
            for (int nt = 0; nt < 8; nt++) {
                float p0 = ex2f(s[nt][0] - mn0);
                float p1 = ex2f(s[nt][1] - mn0);
                float p2 = ex2f(s[nt][2] - mn1);
                float p3 = ex2f(s[nt][3] - mn1);
                pa[nt >> 1][(nt & 1) * 2 + 0] = pack_h2(p0, p1);
                pa[nt >> 1][(nt & 1) * 2 + 1] = pack_h2(p2, p3);
            }

            // conditional rescale (incl. row-sum tile 8)
            bool skip = __all_sync(0xffffffffu, (sc0 == 1.f) && (sc1 == 1.f));
            if (!skip) {
#pragma unroll
                for (int nt = 0; nt < 9; nt++) {
                    o[nt][0] *= sc0; o[nt][1] *= sc0;
                    o[nt][2] *= sc1; o[nt][3] *= sc1;
                }
            }
        }

        // ---- O += P V  (Vt rows = d; rows 64..71 = ones/zeros -> row sum) ----
#pragma unroll
        for (int ks = 0; ks < 4; ks++) {
            uint32_t bf[9][2];
#pragma unroll
            for (int nt = 0; nt < 9; nt++) {
                bf[nt][0] = *(const uint32_t*)&Vs[(nt * 8 + gr) * VPH + ks * 16 + 2 * tq];
                bf[nt][1] = *(const uint32_t*)&Vs[(nt * 8 + gr) * VPH + ks * 16 + 2 * tq + 8];
            }
#pragma unroll
            for (int nt = 0; nt < 9; nt++)
                mma_f16(o[nt], pa[ks], bf[nt]);
        }
    }

    // epilogue: row sums live in o[8][0/2] of the tq==0 lane of each quad
    {
        float ls0 = __shfl_sync(0xffffffffu, o[8][0], lane & ~3);
        float ls1 = __shfl_sync(0xffffffffu, o[8][2], lane & ~3);
        float inv0 = 1.f / ls0;
        float inv1 = 1.f / ls1;
        __half* z0 = z + (size_t)(b * NN + qrow) * DD + h * DK;
        __half* z1 = z0 + (size_t)8 * DD;
#pragma unroll
        for (int nt = 0; nt < 8; nt++) {
            int d0 = nt * 8 + 2 * tq;
            *(uint32_t*)(z0 + d0) = pack_h2(o[nt][0] * inv0, o[nt][1] * inv0);
            *(uint32_t*)(z1 + d0) = pack_h2(o[nt][2] * inv1, o[nt][3] * inv1);
        }
    }
}

// ---------------------------------------------------------------------------
extern "C" void kernel_launch(void* const* d_in, const int* in_sizes, int n_in,
                              void* d_out, int out_size)
{
    const float* x    = (const float*)d_in[0];
    const float* mask = (const float*)d_in[1];
    const float* Wq   = (const float*)d_in[2];
    const float* Wk   = (const float*)d_in[3];
    const float* Wv   = (const float*)d_in[4];
    const float* U    = (const float*)d_in[5];
    const float* Wp   = (const float*)d_in[6];
    const int*   rbt  = (const int*)d_in[7];
    float* out = (float*)d_out;
    (void)in_sizes; (void)n_in; (void)out_size;

    __half *xh, *wB, *wph, *qkv, *vt, *zh, *maskh;
    cudaGetSymbolAddress((void**)&xh, g_xh);
    cudaGetSymbolAddress((void**)&wB, g_wB);
    cudaGetSymbolAddress((void**)&wph, g_wph);
    cudaGetSymbolAddress((void**)&qkv, g_qkv);
    cudaGetSymbolAddress((void**)&vt, g_vt);
    cudaGetSymbolAddress((void**)&zh, g_zh);
    cudaGetSymbolAddress((void**)&maskh, g_maskh);

    static bool attr_set = false;
    if (!attr_set) {
        cudaFuncSetAttribute(hgemm,
                             cudaFuncAttributeMaxDynamicSharedMemorySize,
                             HGEMM_SMEM);
        cudaFuncSetAttribute(attn_h_kernel,
                             cudaFuncAttributeMaxDynamicSharedMemorySize,
                             ATT_SMEM);
        attr_set = true;
    }

    // 0. conversions to fp16 (mask pre-scaled by log2(e) for base-2 softmax)
    tohalf_kernel<<<(BN * DD / 4 + 255) / 256, 256>>>(x, xh, BN * DD / 4, 1.f);
    tohalf_kernel<<<(DD * DD / 4 + 255) / 256, 256>>>(Wv, wB + DD * DD,
                                                      DD * DD / 4, 1.f);
    tohalf_kernel<<<(DD * DD / 4 + 255) / 256, 256>>>(Wp, wph, DD * DD / 4, 1.f);
    tohalf_kernel<<<(NN * NN / 4 + 255) / 256, 256>>>(mask, maskh, NN * NN / 4,
                                                      LOG2E);

    // 1. effective low-rank weights (fp16, K-major, into wB rows 0..1023)
    weff_h_kernel<<<dim3(DD / 256, HH, 4), 256>>>(Wq, Wk, U, wB);

    // 2. fused q|k|v = x @ wB^T   [4096,1024]x[2048,1024]^T -> fp16
    hgemm<<<dim3(2 * DD / 128, BN / 128), 256, HGEMM_SMEM>>>(
        xh, wB, nullptr, qkv, DD, QLD, 1);

    // 3. transpose v slice to [b][h][d][n]
    vtrans_kernel<<<dim3(NN / 64, HH, BB), 256>>>(qkv, vt);

    // 4. flash attention (fp16 HMMA, 8 warps/CTA, MUFU exp2)
    attn_h_kernel<<<dim3(NN / 128, HH, BB), 256, ATT_SMEM>>>(
        qkv, vt, maskh, rbt, zh);

    // 5. out = z @ Wproj^T (f32 output)
    hgemm<<<dim3(DD / 128, BN / 128), 256, HGEMM_SMEM>>>(
        zh, wph, out, nullptr, DD, DD, 0);
}

// round 14
// speedup vs baseline: 1.0443x; 1.0443x over previous
#include <cuda_runtime.h>
#include <cuda_fp16.h>
#include <math_constants.h>
#include <cstdint>

// Problem constants
constexpr int BB  = 2;
constexpr int NN  = 2048;
constexpr int DD  = 1024;
constexpr int HH  = 16;
constexpr int RR  = 32;
constexpr int DK  = 64;
constexpr int HR  = HH * RR;      // 512
constexpr int BN  = BB * NN;      // 4096
constexpr int QLD = 2 * DD;       // fused qkv row stride (2048)

constexpr float LOG2E = 1.4426950408889634f;

// Scratch (device globals; no allocation allowed)
__device__ __half g_xh[BN * DD];            // x fp16
__device__ __half g_wB[2 * DD * DD];        // rows 0..511 WqT | 512..1023 WkT | 1024..2047 Wv
__device__ __half g_wph[DD * DD];           // Wproj fp16 [n][k]
__device__ __half g_qkv[BN * QLD];          // cols: 0..511 q | 512..1023 k | 1024..2047 v
__device__ __half g_vt[BB * HH * DK * NN];  // [b][h][d][n]
__device__ __half g_zh[BN * DD];            // [bn][h*64+d]
__device__ __half g_maskh[NN * NN];         // mask * log2(e), fp16

// ---------------------------------------------------------------------------
// helpers
// ---------------------------------------------------------------------------
__device__ __forceinline__ uint32_t smem_u32(const void* p) {
    uint32_t a;
    asm("{ .reg .u64 t; cvta.to.shared.u64 t, %1; cvt.u32.u64 %0, t; }"
        : "=r"(a) : "l"(p));
    return a;
}
__device__ __forceinline__ void cp16(uint32_t s, const void* g) {
    asm volatile("cp.async.cg.shared.global [%0], [%1], 16;"
                 :: "r"(s), "l"(g) : "memory");
}
#define CP_COMMIT() asm volatile("cp.async.commit_group;" ::: "memory")
#define CP_WAIT0()  asm volatile("cp.async.wait_group 0;" ::: "memory")
#define CP_WAIT1()  asm volatile("cp.async.wait_group 1;" ::: "memory")

// single-MUFU exp2 f32
__device__ __forceinline__ float ex2f(float x) {
    float y; asm("ex2.approx.ftz.f32 %0, %1;" : "=f"(y) : "f"(x)); return y;
}
// packed half2 exp2: ONE MUFU op -> two exps, result already fp16x2
__device__ __forceinline__ uint32_t ex2h2(uint32_t x) {
    uint32_t y; asm("ex2.approx.f16x2 %0, %1;" : "=r"(y) : "r"(x)); return y;
}

// D += A(16x16,row) * B(16x8,col)   fp16 inputs, f32 accum
__device__ __forceinline__ void mma_f16(float d[4], const uint32_t a[4],
                                        const uint32_t b[2]) {
    asm volatile(
        "mma.sync.aligned.m16n8k16.row.col.f32.f16.f16.f32 "
        "{%0,%1,%2,%3}, {%4,%5,%6,%7}, {%8,%9}, {%0,%1,%2,%3};"
        : "+f"(d[0]), "+f"(d[1]), "+f"(d[2]), "+f"(d[3])
        : "r"(a[0]), "r"(a[1]), "r"(a[2]), "r"(a[3]), "r"(b[0]), "r"(b[1]));
}
__device__ __forceinline__ uint32_t pack_h2(float a, float b) {
    __half2 h = __floats2half2_rn(a, b);
    return *(uint32_t*)&h;
}

// ---------------------------------------------------------------------------
// f32 -> f16 conversion (with optional scale)
// ---------------------------------------------------------------------------
__global__ void tohalf_kernel(const float* __restrict__ src,
                              __half* __restrict__ dst, int n4, float scale)
{
    int i = blockIdx.x * blockDim.x + threadIdx.x;
    if (i < n4) {
        float4 v = ((const float4*)src)[i];
        uint2 o;
        o.x = pack_h2(v.x * scale, v.y * scale);
        o.y = pack_h2(v.z * scale, v.w * scale);
        ((uint2*)dst)[i] = o;
    }
}

// ---------------------------------------------------------------------------
// Effective low-rank weights -> fp16 into g_wB:
// wB[sel*512 + h*32 + r, d] = sum_kk Wsel[(h*64+kk), d] * U[kk, r]
// grid (DD/256, HH, 4): z = sel*2 + rhalf
// ---------------------------------------------------------------------------
__global__ void weff_h_kernel(const float* __restrict__ Wq,
                              const float* __restrict__ Wk,
                              const float* __restrict__ U,
                              __half* __restrict__ wB)
{
    __shared__ float Us[DK][RR];
    const int d = blockIdx.x * 256 + threadIdx.x;
    const int h = blockIdx.y;
    const int sel = blockIdx.z >> 1, rh = blockIdx.z & 1;
    const float* W = sel ? Wk : Wq;
    for (int i = threadIdx.x; i < DK * RR; i += 256)
        Us[i >> 5][i & 31] = U[i];
    __syncthreads();

    float w[DK];
#pragma unroll
    for (int kk = 0; kk < DK; kk++)
        w[kk] = W[(size_t)(h * DK + kk) * DD + d];
#pragma unroll 1
    for (int ri = 0; ri < 16; ri++) {
        int r = rh * 16 + ri;
        float s = 0.f;
#pragma unroll
        for (int kk = 0; kk < DK; kk++) s = fmaf(w[kk], Us[kk][r], s);
        wB[(size_t)(sel * HR + h * RR + r) * DD + d] = __float2half(s);
    }
}

// ---------------------------------------------------------------------------
// V transpose: qkv v-cols [bn][1024 + h*64+d] -> vt[b][h][d][n]
// grid (NN/64, HH, BB), block 256
// ---------------------------------------------------------------------------
__global__ void vtrans_kernel(const __half* __restrict__ qkv,
                              __half* __restrict__ vt)
{
    __shared__ __half ts[64][72];
    const int b = blockIdx.z, h = blockIdx.y, n0 = blockIdx.x * 64;
    const int t = threadIdx.x;
#pragma unroll
    for (int s = 0; s < 2; s++) {
        int f = t + 256 * s, row = f >> 3, cc = (f & 7) * 8;
        *(uint4*)&ts[row][cc] = *(const uint4*)
            (qkv + (size_t)(b * NN + n0 + row) * QLD + DD + h * DK + cc);
    }
    __syncthreads();
#pragma unroll
    for (int s = 0; s < 2; s++) {
        int f = t + 256 * s, dr = f >> 3, cc = (f & 7) * 8;
        __half tmp[8];
#pragma unroll
        for (int j = 0; j < 8; j++) tmp[j] = ts[cc + j][dr];
        *(uint4*)(vt + ((size_t)((b * HH + h) * DK + dr)) * NN + n0 + cc) =
            *(uint4*)tmp;
    }
}

// ---------------------------------------------------------------------------
// fp16 HMMA GEMM with cp.async double buffering (scalar LDS fragments).
// C[M,N] = A[M,K] @ B[N,K]^T   (A,B half, K-major)
// grid (N/128, M/128), block 256 (8 warps), warp tile 32x64, K-chunk 64.
// ---------------------------------------------------------------------------
constexpr int HP      = 72;                 // smem row pitch (halfs)
constexpr int HTILE_B = 128 * HP * 2;       // 18432 bytes
constexpr int HGEMM_SMEM = 2 * 2 * HTILE_B; // 73728

__global__ __launch_bounds__(256, 2) void hgemm(
    const __half* __restrict__ A, const __half* __restrict__ B,
    float* __restrict__ Cf, __half* __restrict__ Ch, int K, int ldc,
    int out_half)
{
    extern __shared__ char sm[];
    const uint32_t smb = smem_u32(sm);
    const int t = threadIdx.x, wid = t >> 5, lane = t & 31;
    const int gr = lane >> 2, tq = lane & 3;
    const int wm = wid & 3, wn = wid >> 2;
    const int brow = blockIdx.y * 128, bcol = blockIdx.x * 128;

    const __half* Ab = A + (size_t)brow * K;
    const __half* Bb = B + (size_t)bcol * K;
    const int row_l = t >> 3, cc_l = (t & 7) * 8;

    float acc[2][8][4] = {};
    const int nc = K / 64;

    auto issue = [&](int c) {
        const int buf = c & 1, k0 = c * 64;
        uint32_t as = smb + (uint32_t)buf * (2 * HTILE_B);
        uint32_t bs = as + HTILE_B;
#pragma unroll
        for (int s = 0; s < 4; s++) {
            int row = row_l + 32 * s;
            cp16(as + (row * HP + cc_l) * 2, Ab + (size_t)row * K + k0 + cc_l);
            cp16(bs + (row * HP + cc_l) * 2, Bb + (size_t)row * K + k0 + cc_l);
        }
        CP_COMMIT();
    };

    issue(0);
    for (int c = 0; c < nc; c++) {
        __syncthreads();
        if (c + 1 < nc) { issue(c + 1); CP_WAIT1(); }
        else            { CP_WAIT0(); }
        __syncthreads();

        const __half* As = (const __half*)(sm + (c & 1) * 2 * HTILE_B);
        const __half* Bs = (const __half*)(sm + (c & 1) * 2 * HTILE_B + HTILE_B);
#pragma unroll
        for (int ks = 0; ks < 4; ks++) {
            const int kb = ks * 16;
            uint32_t af[2][4], bf[8][2];
#pragma unroll
            for (int mt = 0; mt < 2; mt++) {
                int rb0 = wm * 32 + mt * 16 + gr;
                af[mt][0] = *(const uint32_t*)&As[rb0 * HP + kb + 2 * tq];
                af[mt][1] = *(const uint32_t*)&As[(rb0 + 8) * HP + kb + 2 * tq];
                af[mt][2] = *(const uint32_t*)&As[rb0 * HP + kb + 2 * tq + 8];
                af[mt][3] = *(const uint32_t*)&As[(rb0 + 8) * HP + kb + 2 * tq + 8];
            }
#pragma unroll
            for (int nt = 0; nt < 8; nt++) {
                int cb = wn * 64 + nt * 8 + gr;
                bf[nt][0] = *(const uint32_t*)&Bs[cb * HP + kb + 2 * tq];
                bf[nt][1] = *(const uint32_t*)&Bs[cb * HP + kb + 2 * tq + 8];
            }
#pragma unroll
            for (int mt = 0; mt < 2; mt++)
#pragma unroll
                for (int nt = 0; nt < 8; nt++)
                    mma_f16(acc[mt][nt], af[mt], bf[nt]);
        }
    }

#pragma unroll
    for (int mt = 0; mt < 2; mt++) {
        int r0 = brow + wm * 32 + mt * 16 + gr;
#pragma unroll
        for (int nt = 0; nt < 8; nt++) {
            int col = bcol + wn * 64 + nt * 8 + 2 * tq;
            if (out_half) {
                *(uint32_t*)(Ch + (size_t)r0 * ldc + col) =
                    pack_h2(acc[mt][nt][0], acc[mt][nt][1]);
                *(uint32_t*)(Ch + (size_t)(r0 + 8) * ldc + col) =
                    pack_h2(acc[mt][nt][2], acc[mt][nt][3]);
            } else {
                *(float2*)(Cf + (size_t)r0 * ldc + col) =
                    make_float2(acc[mt][nt][0], acc[mt][nt][1]);
                *(float2*)(Cf + (size_t)(r0 + 8) * ldc + col) =
                    make_float2(acc[mt][nt][2], acc[mt][nt][3]);
            }
        }
    }
}

// ---------------------------------------------------------------------------
// Flash attention, fp16 HMMA, register-resident P, base-2 softmax with
// PACKED f16x2 MUFU exp (one EX2 per two elements, result = P fragment),
// ones-column row sums, diagonal-aware ALiBi, conditional O rescale.
// grid (N/128, H, B), block 128 (4 warps), warp = 32 query rows (2 m-tiles).
// KV chunk = 64 keys, cp.async double buffered.
// SMEM: 2 stages x (K[64 keys][40h] + Vt[72 d-rows][72h])
// ---------------------------------------------------------------------------
constexpr int KPH = 40, VPH = 72;
constexpr int KTB = 64 * KPH * 2;        // 5120
constexpr int VTB = 72 * VPH * 2;        // 10368 (rows 64..71 = ones/zeros)
constexpr int STG = KTB + VTB;           // 15488
constexpr int ATT_SMEM = 2 * STG;        // 30976

__global__ __launch_bounds__(128) void attn_h_kernel(
    const __half* __restrict__ qkv, const __half* __restrict__ vt,
    const __half* __restrict__ mask, const int* __restrict__ rbt,
    __half* __restrict__ z)
{
    extern __shared__ char sma[];
    const uint32_t smb = smem_u32(sma);

    const int t = threadIdx.x, wid = t >> 5, lane = t & 31;
    const int gr = lane >> 2, tq = lane & 3;
    const int b = blockIdx.z, h = blockIdx.y;
    const int q0 = blockIdx.x * 128;

    // base-2 domain: logits scaled by log2(e)
    const float qs     = 0.125f * LOG2E;
    const float slope2 = exp2f(-0.5f * (float)(h + 1)) * LOG2E;
    const int   Ttok   = rbt[0];

    // init ones rows (64..71) of both V stage buffers; row 64 = 1, rest 0
#pragma unroll
    for (int bi = 0; bi < 2; bi++) {
        __half* vsp = (__half*)(sma + bi * STG + KTB);
        for (int i = t; i < 8 * VPH; i += 128) {
            int row = 64 + i / VPH;
            vsp[row * VPH + (i % VPH)] =
                (row == 64) ? __float2half(1.f) : __float2half(0.f);
        }
    }

    // Q fragments (raw fp16)
    uint32_t qa[2][2][4];
    int qrow[2];
#pragma unroll
    for (int mt = 0; mt < 2; mt++) {
        qrow[mt] = q0 + wid * 32 + mt * 16 + gr;
        const __half* q0p = qkv + (size_t)(b * NN + qrow[mt]) * QLD + h * RR;
        const __half* q1p = q0p + (size_t)8 * QLD;
#pragma unroll
        for (int ks = 0; ks < 2; ks++) {
            qa[mt][ks][0] = *(const uint32_t*)&q0p[ks * 16 + 2 * tq];
            qa[mt][ks][1] = *(const uint32_t*)&q1p[ks * 16 + 2 * tq];
            qa[mt][ks][2] = *(const uint32_t*)&q0p[ks * 16 + 2 * tq + 8];
            qa[mt][ks][3] = *(const uint32_t*)&q1p[ks * 16 + 2 * tq + 8];
        }
    }

    auto issue = [&](int c) {
        const int buf = c & 1, kc = c * 64;
        uint32_t ksm = smb + (uint32_t)buf * STG;
        uint32_t vsm = ksm + KTB;
        const __half* kb = qkv + (size_t)(b * NN + kc) * QLD + HR + h * RR;
        const __half* vb = vt + ((size_t)((b * HH + h) * DK)) * NN + kc;
#pragma unroll
        for (int s = 0; s < 2; s++) {
            int f = t + 128 * s, row = f >> 2, cc = (f & 3) * 8;
            cp16(ksm + (row * KPH + cc) * 2, kb + (size_t)row * QLD + cc);
        }
#pragma unroll
        for (int s = 0; s < 4; s++) {
            int f = t + 128 * s, row = f >> 3, cc = (f & 7) * 8;
            cp16(vsm + (row * VPH + cc) * 2, vb + (size_t)row * NN + cc);
        }
        CP_COMMIT();
    };

    float o[2][9][4] = {};                 // tile 8 = row-sum (ones column)
    float mrun[2][2] = {{-1e30f, -1e30f}, {-1e30f, -1e30f}};

    const int nch = NN / 64;
    issue(0);
    for (int c = 0; c < nch; c++) {
        const int kc = c * 64;
        __syncthreads();
        if (c + 1 < nch) { issue(c + 1); CP_WAIT1(); }
        else             { CP_WAIT0(); }
        __syncthreads();

        const __half* Ks = (const __half*)(sma + (c & 1) * STG);
        const __half* Vs = (const __half*)(sma + (c & 1) * STG + KTB);

        // ---- S = Q K^T ----
        float s[2][8][4] = {};
#pragma unroll
        for (int ks = 0; ks < 2; ks++) {
            uint32_t bf[8][2];
#pragma unroll
            for (int nt = 0; nt < 8; nt++) {
                bf[nt][0] = *(const uint32_t*)&Ks[(nt * 8 + gr) * KPH + ks * 16 + 2 * tq];
                bf[nt][1] = *(const uint32_t*)&Ks[(nt * 8 + gr) * KPH + ks * 16 + 2 * tq + 8];
            }
#pragma unroll
            for (int mt = 0; mt < 2; mt++)
#pragma unroll
                for (int nt = 0; nt < 8; nt++)
                    mma_f16(s[mt][nt], qa[mt][ks], bf[nt]);
        }

        // ---- scale + bias (diagonal-aware) + online softmax + P pack ----
        uint32_t pa[2][4][4];
#pragma unroll
        for (int mt = 0; mt < 2; mt++) {
            const int base = q0 + wid * 32 + mt * 16;   // warp-uniform min row
            const int i0 = qrow[mt], i1 = i0 + 8;
            const float adj0 = (float)(i0 + Ttok - NN);
            const float adj1 = (float)(i1 + Ttok - NN);
            const __half* mr0 = mask + (size_t)i0 * NN;
            const __half* mr1 = mask + (size_t)i1 * NN;

            if (kc + 63 <= base + Ttok - NN) {
                // all keys at/below diagonal for every row: dist = 0
#pragma unroll
                for (int nt = 0; nt < 8; nt++) {
                    int j0 = kc + nt * 8 + 2 * tq;
                    float2 mk0 = __half22float2(*(const __half2*)(mr0 + j0));
                    float2 mk1 = __half22float2(*(const __half2*)(mr1 + j0));
                    s[mt][nt][0] = fmaf(s[mt][nt][0], qs, mk0.x);
                    s[mt][nt][1] = fmaf(s[mt][nt][1], qs, mk0.y);
                    s[mt][nt][2] = fmaf(s[mt][nt][2], qs, mk1.x);
                    s[mt][nt][3] = fmaf(s[mt][nt][3], qs, mk1.y);
                }
            } else if (kc >= base + 15 + Ttok - NN) {
                // all keys above diagonal: dist = j - adj (no clamp)
                const float c0 = slope2 * adj0, c1 = slope2 * adj1;
#pragma unroll
                for (int nt = 0; nt < 8; nt++) {
                    int j0 = kc + nt * 8 + 2 * tq;
                    float2 mk0 = __half22float2(*(const __half2*)(mr0 + j0));
                    float2 mk1 = __half22float2(*(const __half2*)(mr1 + j0));
                    float j0f = (float)j0, j1f = j0f + 1.f;
                    s[mt][nt][0] = fmaf(s[mt][nt][0], qs,
                                        fmaf(j0f, -slope2, mk0.x + c0));
                    s[mt][nt][1] = fmaf(s[mt][nt][1], qs,
                                        fmaf(j1f, -slope2, mk0.y + c0));
                    s[mt][nt][2] = fmaf(s[mt][nt][2], qs,
                                        fmaf(j0f, -slope2, mk1.x + c1));
                    s[mt][nt][3] = fmaf(s[mt][nt][3], qs,
                                        fmaf(j1f, -slope2, mk1.y + c1));
                }
            } else {
                // mixed chunk (diagonal crossing)
#pragma unroll
                for (int nt = 0; nt < 8; nt++) {
                    int j0 = kc + nt * 8 + 2 * tq;
                    float2 mk0 = __half22float2(*(const __half2*)(mr0 + j0));
                    float2 mk1 = __half22float2(*(const __half2*)(mr1 + j0));
                    float j0f = (float)j0, j1f = j0f + 1.f;
                    s[mt][nt][0] = fmaf(s[mt][nt][0], qs,
                                        mk0.x - slope2 * fmaxf(j0f - adj0, 0.f));
                    s[mt][nt][1] = fmaf(s[mt][nt][1], qs,
                                        mk0.y - slope2 * fmaxf(j1f - adj0, 0.f));
                    s[mt][nt][2] = fmaf(s[mt][nt][2], qs,
                                        mk1.x - slope2 * fmaxf(j0f - adj1, 0.f));
                    s[mt][nt][3] = fmaf(s[mt][nt][3], qs,
                                        mk1.y - slope2 * fmaxf(j1f - adj1, 0.f));
                }
            }

            float lm0 = -1e30f, lm1 = -1e30f;
#pragma unroll
            for (int nt = 0; nt < 8; nt++) {
                lm0 = fmaxf(lm0, fmaxf(s[mt][nt][0], s[mt][nt][1]));
                lm1 = fmaxf(lm1, fmaxf(s[mt][nt][2], s[mt][nt][3]));
            }
            lm0 = fmaxf(lm0, __shfl_xor_sync(0xffffffffu, lm0, 1));
            lm0 = fmaxf(lm0, __shfl_xor_sync(0xffffffffu, lm0, 2));
            lm1 = fmaxf(lm1, __shfl_xor_sync(0xffffffffu, lm1, 1));
            lm1 = fmaxf(lm1, __shfl_xor_sync(0xffffffffu, lm1, 2));

            float mn0 = fmaxf(mrun[mt][0], lm0);
            float mn1 = fmaxf(mrun[mt][1], lm1);
            float sc0 = ex2f(mrun[mt][0] - mn0);
            float sc1 = ex2f(mrun[mt][1] - mn1);
            mrun[mt][0] = mn0; mrun[mt][1] = mn1;

            // packed exp: subtract max in f32, pack to f16x2, ONE MUFU per pair
#pragma unroll
            for (int nt = 0; nt < 8; nt++) {
                uint32_t a01 = pack_h2(s[mt][nt][0] - mn0, s[mt][nt][1] - mn0);
                uint32_t a23 = pack_h2(s[mt][nt][2] - mn1, s[mt][nt][3] - mn1);
                pa[mt][nt >> 1][(nt & 1) * 2 + 0] = ex2h2(a01);
                pa[mt][nt >> 1][(nt & 1) * 2 + 1] = ex2h2(a23);
            }

            // conditional rescale (incl. row-sum tile 8)
            bool skip = __all_sync(0xffffffffu,
                                   (sc0 == 1.f) && (sc1 == 1.f));
            if (!skip) {
#pragma unroll
                for (int nt = 0; nt < 9; nt++) {
                    o[mt][nt][0] *= sc0; o[mt][nt][1] *= sc0;
                    o[mt][nt][2] *= sc1; o[mt][nt][3] *= sc1;
                }
            }
        }

        // ---- O += P V  (Vt rows = d; rows 64..71 = ones/zeros -> row sum) ----
#pragma unroll
        for (int ks = 0; ks < 4; ks++) {
            uint32_t bf[9][2];
#pragma unroll
            for (int nt = 0; nt < 9; nt++) {
                bf[nt][0] = *(const uint32_t*)&Vs[(nt * 8 + gr) * VPH + ks * 16 + 2 * tq];
                bf[nt][1] = *(const uint32_t*)&Vs[(nt * 8 + gr) * VPH + ks * 16 + 2 * tq + 8];
            }
#pragma unroll
            for (int mt = 0; mt < 2; mt++)
#pragma unroll
                for (int nt = 0; nt < 9; nt++)
                    mma_f16(o[mt][nt], pa[mt][ks], bf[nt]);
        }
    }

    // epilogue: row sums live in o[mt][8][0/2] of the tq==0 lane of each quad
#pragma unroll
    for (int mt = 0; mt < 2; mt++) {
        float ls0 = __shfl_sync(0xffffffffu, o[mt][8][0], lane & ~3);
        float ls1 = __shfl_sync(0xffffffffu, o[mt][8][2], lane & ~3);
        float inv0 = 1.f / ls0;
        float inv1 = 1.f / ls1;
        __half* z0 = z + (size_t)(b * NN + qrow[mt]) * DD + h * DK;
        __half* z1 = z0 + (size_t)8 * DD;
#pragma unroll
        for (int nt = 0; nt < 8; nt++) {
            int d0 = nt * 8 + 2 * tq;
            *(uint32_t*)(z0 + d0) = pack_h2(o[mt][nt][0] * inv0,
                                            o[mt][nt][1] * inv0);
            *(uint32_t*)(z1 + d0) = pack_h2(o[mt][nt][2] * inv1,
                                            o[mt][nt][3] * inv1);
        }
    }
}

// ---------------------------------------------------------------------------
extern "C" void kernel_launch(void* const* d_in, const int* in_sizes, int n_in,
                              void* d_out, int out_size)
{
    const float* x    = (const float*)d_in[0];
    const float* mask = (const float*)d_in[1];
    const float* Wq   = (const float*)d_in[2];
    const float* Wk   = (const float*)d_in[3];
    const float* Wv   = (const float*)d_in[4];
    const float* U    = (const float*)d_in[5];
    const float* Wp   = (const float*)d_in[6];
    const int*   rbt  = (const int*)d_in[7];
    float* out = (float*)d_out;
    (void)in_sizes; (void)n_in; (void)out_size;

    __half *xh, *wB, *wph, *qkv, *vt, *zh, *maskh;
    cudaGetSymbolAddress((void**)&xh, g_xh);
    cudaGetSymbolAddress((void**)&wB, g_wB);
    cudaGetSymbolAddress((void**)&wph, g_wph);
    cudaGetSymbolAddress((void**)&qkv, g_qkv);
    cudaGetSymbolAddress((void**)&vt, g_vt);
    cudaGetSymbolAddress((void**)&zh, g_zh);
    cudaGetSymbolAddress((void**)&maskh, g_maskh);

    static bool attr_set = false;
    if (!attr_set) {
        cudaFuncSetAttribute(hgemm,
                             cudaFuncAttributeMaxDynamicSharedMemorySize,
                             HGEMM_SMEM);
        cudaFuncSetAttribute(attn_h_kernel,
                             cudaFuncAttributeMaxDynamicSharedMemorySize,
                             ATT_SMEM);
        attr_set = true;
    }

    // 0. conversions to fp16 (mask pre-scaled by log2(e) for base-2 softmax)
    tohalf_kernel<<<(BN * DD / 4 + 255) / 256, 256>>>(x, xh, BN * DD / 4, 1.f);
    tohalf_kernel<<<(DD * DD / 4 + 255) / 256, 256>>>(Wv, wB + DD * DD,
                                                      DD * DD / 4, 1.f);
    tohalf_kernel<<<(DD * DD / 4 + 255) / 256, 256>>>(Wp, wph, DD * DD / 4, 1.f);
    tohalf_kernel<<<(NN * NN / 4 + 255) / 256, 256>>>(mask, maskh, NN * NN / 4,
                                                      LOG2E);

    // 1. effective low-rank weights (fp16, K-major, into wB rows 0..1023)
    weff_h_kernel<<<dim3(DD / 256, HH, 4), 256>>>(Wq, Wk, U, wB);

    // 2. fused q|k|v = x @ wB^T   [4096,1024]x[2048,1024]^T -> fp16
    hgemm<<<dim3(2 * DD / 128, BN / 128), 256, HGEMM_SMEM>>>(
        xh, wB, nullptr, qkv, DD, QLD, 1);

    // 3. transpose v slice to [b][h][d][n]
    vtrans_kernel<<<dim3(NN / 64, HH, BB), 256>>>(qkv, vt);

    // 4. flash attention (fp16 HMMA, packed f16x2 MUFU exp)
    attn_h_kernel<<<dim3(NN / 128, HH, BB), 128, ATT_SMEM>>>(
        qkv, vt, maskh, rbt, zh);

    // 5. out = z @ Wproj^T (f32 output)
    hgemm<<<dim3(DD / 128, BN / 128), 256, HGEMM_SMEM>>>(
        zh, wph, out, nullptr, DD, DD, 0);
}